// round 16
// baseline (speedup 1.0000x reference)
#include <cuda_runtime.h>
#include <cuda_fp16.h>
#include <math.h>
#include <stdint.h>

// Static problem config
#define N_TOK 8192      // B*T = 4*2048
#define D_DIM 1024
#define FF_DIM 4096
#define N_EXP 8
#define NK 16384        // N_TOK * TOP_K
#define CHUNK 2048      // NK / N_EXP
#define STAGES 3

// ---------------- device scratch (no allocations allowed) ----------------
__device__ __align__(256) __half g_h[(size_t)NK * FF_DIM];      // fp16 gelu(perm @ w1)
__device__ __align__(256) float  g_y[(size_t)NK * D_DIM];       // h @ w2 (fp32)
__device__ __align__(256) __half g_xh[(size_t)N_TOK * D_DIM];   // fp16(x)
__device__ __align__(256) __half g_w1t[(size_t)N_EXP * (size_t)FF_DIM * D_DIM]; // w1^T fp16
__device__ __align__(256) __half g_w2t[(size_t)N_EXP * (size_t)D_DIM * FF_DIM]; // w2^T fp16
__device__ int   g_eflat[NK];
__device__ float g_wflat[NK];
__device__ int   g_dest[NK];
__device__ int   g_srcrow[NK];

// ---------------- helpers ----------------
__device__ __forceinline__ uint32_t smem_u32(const void* p) {
    return (uint32_t)__cvta_generic_to_shared(p);
}
__device__ __forceinline__ void cp16(uint32_t dst, const void* src) {
    asm volatile("cp.async.cg.shared.global [%0], [%1], 16;" :: "r"(dst), "l"(src));
}
#define LDSM_X4(r0, r1, r2, r3, a) \
    asm volatile("ldmatrix.sync.aligned.m8n8.x4.shared.b16 {%0,%1,%2,%3}, [%4];" \
                 : "=r"(r0), "=r"(r1), "=r"(r2), "=r"(r3) : "r"(a))

// ---------------- 0) weight transpose + fp16 convert: w[E][K][N] -> wt[E][N][K] ----------------
__global__ void transpose_h(const float* __restrict__ w, __half* __restrict__ wt,
                            int K, int N) {
    __shared__ float t[32][33];
    int e = blockIdx.z;
    const float* we = w + (size_t)e * K * N;
    __half* wte = wt + (size_t)e * (size_t)N * K;
    int n0 = blockIdx.x * 32, k0 = blockIdx.y * 32;
    int tx = threadIdx.x, ty = threadIdx.y;  // 32 x 8
#pragma unroll
    for (int i = 0; i < 4; i++)
        t[ty + 8 * i][tx] = we[(size_t)(k0 + ty + 8 * i) * N + n0 + tx];
    __syncthreads();
#pragma unroll
    for (int i = 0; i < 4; i++)
        wte[(size_t)(n0 + ty + 8 * i) * K + k0 + tx] = __float2half_rn(t[tx][ty + 8 * i]);
}

// ---------------- 1) router: logits, top-2, softmax; also emits fp16(x) ----------------
__global__ void router_kernel(const float* __restrict__ x,
                              const float* __restrict__ rw) {
    __shared__ float s_rw[N_EXP * D_DIM];
    int tid = threadIdx.x;
    for (int i = tid; i < N_EXP * D_DIM; i += blockDim.x) s_rw[i] = rw[i];
    __syncthreads();

    int warp = tid >> 5, lane = tid & 31;
    int token = blockIdx.x * (blockDim.x >> 5) + warp;

    const float4* x4 = reinterpret_cast<const float4*>(x + (size_t)token * D_DIM);
    __half2* xh2 = reinterpret_cast<__half2*>(g_xh + (size_t)token * D_DIM);
    float acc[N_EXP];
#pragma unroll
    for (int e = 0; e < N_EXP; e++) acc[e] = 0.f;

    for (int dq = lane; dq < D_DIM / 4; dq += 32) {
        float4 xv = x4[dq];
        xh2[2 * dq]     = __floats2half2_rn(xv.x, xv.y);
        xh2[2 * dq + 1] = __floats2half2_rn(xv.z, xv.w);
#pragma unroll
        for (int e = 0; e < N_EXP; e++) {
            float4 r = reinterpret_cast<const float4*>(s_rw + e * D_DIM)[dq];
            acc[e] += xv.x * r.x + xv.y * r.y + xv.z * r.z + xv.w * r.w;
        }
    }
#pragma unroll
    for (int e = 0; e < N_EXP; e++)
#pragma unroll
        for (int off = 16; off > 0; off >>= 1)
            acc[e] += __shfl_xor_sync(0xffffffffu, acc[e], off);

    if (lane == 0) {
        int i0 = 0; float v0 = acc[0];
#pragma unroll
        for (int e = 1; e < N_EXP; e++) if (acc[e] > v0) { v0 = acc[e]; i0 = e; }
        int i1 = -1; float v1 = -INFINITY;
#pragma unroll
        for (int e = 0; e < N_EXP; e++)
            if (e != i0 && acc[e] > v1) { v1 = acc[e]; i1 = e; }
        float e1 = expf(v1 - v0);
        float inv = 1.f / (1.f + e1);
        g_eflat[2 * token]     = i0;
        g_eflat[2 * token + 1] = i1;
        g_wflat[2 * token]     = inv;
        g_wflat[2 * token + 1] = e1 * inv;
    }
}

// ---------------- 2) stable sort-by-expert rank scan (1 block, 1024 thr) ----------------
__global__ void scan_kernel() {
    __shared__ int s_cnt[N_EXP];
    __shared__ int s_cur[N_EXP];
    __shared__ int s_whist[32][N_EXP];   // 32 warps x 8 experts
    int tid = threadIdx.x;               // 1024 threads
    int warp = tid >> 5, lane = tid & 31;

    if (tid < N_EXP) s_cnt[tid] = 0;
    __syncthreads();
    for (int i = tid; i < NK; i += 1024) atomicAdd(&s_cnt[g_eflat[i]], 1);
    __syncthreads();
    if (tid == 0) {
        int off = 0;
        for (int e = 0; e < N_EXP; e++) { int c = s_cnt[e]; s_cur[e] = off; off += c; }
    }
    __syncthreads();

    for (int base = 0; base < NK; base += 1024) {
        int i = base + tid;
        int e = g_eflat[i];
        unsigned mask = __match_any_sync(0xffffffffu, e);
        int rank = __popc(mask & ((1u << lane) - 1u));
        int leader = __ffs(mask) - 1;

        if (tid < 32 * N_EXP) ((int*)s_whist)[tid] = 0;
        __syncthreads();
        if (lane == leader) s_whist[warp][e] = __popc(mask);
        __syncthreads();

        int pre = 0;
        for (int w = 0; w < warp; w++) pre += s_whist[w][e];
        int p = s_cur[e] + pre + rank;
        g_dest[i] = p;
        g_srcrow[p] = i >> 1;
        __syncthreads();
        if (tid < N_EXP) {
            int tot = 0;
            for (int w = 0; w < 32; w++) tot += s_whist[w][tid];
            s_cur[tid] += tot;
        }
        __syncthreads();
    }
}

// ---------------- 3) fp16 mma.sync GEMM (m16n8k16 HMMA) ----------------
// C[M x N] = op(A-rows @ Bt[expert]^T), A/Bt fp16, Bt [E][N][K] K-major.
// CTA tile 128x256, BK=64 (128B rows), 3-stage cp.async, 8 warps x (64x64),
// fp32 accumulate. SW128 swizzle; ldmatrix.x4 b16 fragments.
template <bool GATHER, bool GELU_OUT>
__global__ void __launch_bounds__(256)
hgemm(const __half* __restrict__ A, const __half* __restrict__ Bt,
      void* __restrict__ Cout, int K, int N) {
    extern __shared__ __align__(1024) char smem[];
    const uint32_t STAGE = 49152;        // 16KB A + 32KB B per stage

    int tid = threadIdx.x;
    int lane = tid & 31, wid = tid >> 5;
    int m0 = blockIdx.y * 128, n0 = blockIdx.x * 256;
    int expert = m0 / CHUNK;
    const __half* Be = Bt + (size_t)expert * (size_t)N * K;

    // ---- loader: 4 A rows + 8 B rows per thread, one 16B chunk each ----
    int lr = tid >> 3;          // row base 0..31 (rows lr + 32*i)
    int lc = tid & 7;           // 16B chunk (8 halves) within 128B row
    const __half* ap[4];
    const __half* bp0 = Be + (size_t)(n0 + lr) * K + lc * 8;
    size_t bstride = (size_t)32 * K;
#pragma unroll
    for (int i = 0; i < 4; i++) {
        int r = lr + 32 * i;
        long asrc = GATHER ? (long)g_srcrow[m0 + r] : (long)(m0 + r);
        ap[i] = A + asrc * (size_t)K + lc * 8;
    }
    uint32_t off0 = lr * 128 + lc * 16;
    uint32_t swz0 = off0 ^ ((off0 >> 3) & 0x70);   // SW128; +32 rows swizzle-invariant
    uint32_t sbase = smem_u32(smem);

    int nIter = K / 64;

    // ---- prologue ----
#pragma unroll
    for (int s = 0; s < STAGES - 1; ++s) {
        uint32_t ab = sbase + s * STAGE + swz0;
        int kk = s * 64;
#pragma unroll
        for (int i = 0; i < 4; i++) cp16(ab + i * 4096, ap[i] + kk);
#pragma unroll
        for (int i = 0; i < 8; i++) cp16(ab + 16384 + i * 4096, bp0 + i * bstride + kk);
        asm volatile("cp.async.commit_group;");
    }

    // ---- compute-side lane addressing (b16 ldmatrix canonical) ----
    int wm = (wid & 1) * 64, wn = (wid >> 1) * 64;
    int  arow = wm + (lane & 7) + ((lane >> 3) & 1) * 8;   // + mt*16
    uint32_t acol = ((lane >> 4) & 1) * 16;                // byte: + ks*32
    uint32_t axor = (arow & 7) << 4;
    int  brow = wn + (lane & 7) + ((lane >> 3) & 1) * 8;   // + g*16
    uint32_t bcol = ((lane >> 4) & 1) * 16;                // byte: + ks*32
    uint32_t bxor = (brow & 7) << 4;

    float acc[4][8][4];
#pragma unroll
    for (int mt = 0; mt < 4; mt++)
#pragma unroll
        for (int nt = 0; nt < 8; nt++)
#pragma unroll
            for (int j = 0; j < 4; j++) acc[mt][nt][j] = 0.f;

#pragma unroll 1
    for (int it = 0; it < nIter; ++it) {
        asm volatile("cp.async.wait_group %0;" :: "n"(STAGES - 2));
        __syncthreads();

        int pre = it + STAGES - 1;
        if (pre < nIter) {
            uint32_t ab = sbase + (pre % STAGES) * STAGE + swz0;
            int kk = pre * 64;
#pragma unroll
            for (int i = 0; i < 4; i++) cp16(ab + i * 4096, ap[i] + kk);
#pragma unroll
            for (int i = 0; i < 8; i++) cp16(ab + 16384 + i * 4096, bp0 + i * bstride + kk);
        }
        asm volatile("cp.async.commit_group;");

        uint32_t abase = sbase + (it % STAGES) * STAGE;
        uint32_t bbase = abase + 16384;
#pragma unroll
        for (int ks = 0; ks < 4; ++ks) {            // 4 x k16
            uint32_t af[4][4];
#pragma unroll
            for (int mt = 0; mt < 4; ++mt) {
                uint32_t addr = abase + (uint32_t)(arow + mt * 16) * 128
                              + (((uint32_t)ks * 32 + acol) ^ axor);
                LDSM_X4(af[mt][0], af[mt][1], af[mt][2], af[mt][3], addr);
            }
            uint32_t bf[16];
#pragma unroll
            for (int g = 0; g < 4; ++g) {           // two n8 tiles per x4
                uint32_t addr = bbase + (uint32_t)(brow + g * 16) * 128
                              + (((uint32_t)ks * 32 + bcol) ^ bxor);
                LDSM_X4(bf[g * 4 + 0], bf[g * 4 + 1], bf[g * 4 + 2], bf[g * 4 + 3], addr);
            }
#pragma unroll
            for (int mt = 0; mt < 4; ++mt)
#pragma unroll
                for (int nt = 0; nt < 8; ++nt) {
                    float* c = acc[mt][nt];
                    uint32_t b0 = bf[(nt >> 1) * 4 + (nt & 1)];
                    uint32_t b1 = bf[(nt >> 1) * 4 + (nt & 1) + 2];
                    asm volatile(
                        "mma.sync.aligned.m16n8k16.row.col.f32.f16.f16.f32 "
                        "{%0,%1,%2,%3}, {%4,%5,%6,%7}, {%8,%9}, {%0,%1,%2,%3};"
                        : "+f"(c[0]), "+f"(c[1]), "+f"(c[2]), "+f"(c[3])
                        : "r"(af[mt][0]), "r"(af[mt][1]), "r"(af[mt][2]), "r"(af[mt][3]),
                          "r"(b0), "r"(b1));
                }
        }
    }

    // ---- epilogue ----
#pragma unroll
    for (int mt = 0; mt < 4; ++mt) {
        int r0 = m0 + wm + mt * 16 + (lane >> 2);
#pragma unroll
        for (int nt = 0; nt < 8; ++nt) {
            int cc = n0 + wn + nt * 8 + (lane & 3) * 2;
            if (GELU_OUT) {
                // gelu in fp32, store fp16 for GEMM2
                __half* C = (__half*)Cout;
                float v[4];
#pragma unroll
                for (int j = 0; j < 4; j++) {
                    float t = acc[mt][nt][j];
                    v[j] = 0.5f * t * (1.f + erff(t * 0.70710678118654752f));
                }
                *reinterpret_cast<__half2*>(C + (size_t)r0 * N + cc)
                    = __floats2half2_rn(v[0], v[1]);
                *reinterpret_cast<__half2*>(C + (size_t)(r0 + 8) * N + cc)
                    = __floats2half2_rn(v[2], v[3]);
            } else {
                float* C = (float*)Cout;
                *reinterpret_cast<float2*>(C + (size_t)r0 * N + cc)
                    = make_float2(acc[mt][nt][0], acc[mt][nt][1]);
                *reinterpret_cast<float2*>(C + (size_t)(r0 + 8) * N + cc)
                    = make_float2(acc[mt][nt][2], acc[mt][nt][3]);
            }
        }
    }
}

// ---------------- 4) weighted unpermute via gather (deterministic) ----------------
__global__ void combine_kernel(float* __restrict__ out) {
    int idx = blockIdx.x * blockDim.x + threadIdx.x;
    int n  = idx >> 8;
    int dq = idx & 255;
    int p0 = g_dest[2 * n], p1 = g_dest[2 * n + 1];
    float w0 = g_wflat[2 * n], w1 = g_wflat[2 * n + 1];
    float4 y0 = reinterpret_cast<const float4*>(g_y + (size_t)p0 * D_DIM)[dq];
    float4 y1 = reinterpret_cast<const float4*>(g_y + (size_t)p1 * D_DIM)[dq];
    float4 r;
    r.x = w0 * y0.x + w1 * y1.x;
    r.y = w0 * y0.y + w1 * y1.y;
    r.z = w0 * y0.z + w1 * y1.z;
    r.w = w0 * y0.w + w1 * y1.w;
    reinterpret_cast<float4*>(out)[idx] = r;
}

// ---------------- launch ----------------
extern "C" void kernel_launch(void* const* d_in, const int* in_sizes, int n_in,
                              void* d_out, int out_size) {
    const float* x  = (const float*)d_in[0];   // [8192, 1024]
    const float* rw = (const float*)d_in[1];   // [8, 1024]
    const float* w1 = (const float*)d_in[2];   // [8, 1024, 4096]
    const float* w2 = (const float*)d_in[3];   // [8, 4096, 1024]
    float* out = (float*)d_out;                // [8192, 1024]

    __half *w1t, *w2t, *hbuf, *xh;
    float *ybuf;
    cudaGetSymbolAddress((void**)&w1t, g_w1t);
    cudaGetSymbolAddress((void**)&w2t, g_w2t);
    cudaGetSymbolAddress((void**)&hbuf, g_h);
    cudaGetSymbolAddress((void**)&ybuf, g_y);
    cudaGetSymbolAddress((void**)&xh, g_xh);

    const int SMEM_DYN = STAGES * 49152;   // 144 KB
    cudaFuncSetAttribute(hgemm<true, true>,
                         cudaFuncAttributeMaxDynamicSharedMemorySize, SMEM_DYN);
    cudaFuncSetAttribute(hgemm<false, false>,
                         cudaFuncAttributeMaxDynamicSharedMemorySize, SMEM_DYN);

    // 0) fp16 weights (+transpose)
    transpose_h<<<dim3(FF_DIM / 32, D_DIM / 32, N_EXP), dim3(32, 8)>>>(w1, w1t, D_DIM, FF_DIM);
    transpose_h<<<dim3(D_DIM / 32, FF_DIM / 32, N_EXP), dim3(32, 8)>>>(w2, w2t, FF_DIM, D_DIM);

    // 1) router (fp32 logits) + fp16(x) emission
    router_kernel<<<N_TOK / 32, 1024>>>(x, rw);

    // 2) stable expert-rank scan
    scan_kernel<<<1, 1024>>>();

    // 3) GEMM1: gather + [16384x1024]@[1024x4096] + gelu -> g_h (fp16)
    hgemm<true, true><<<dim3(FF_DIM / 256, NK / 128), 256, SMEM_DYN>>>(
        xh, w1t, hbuf, D_DIM, FF_DIM);

    // 4) GEMM2: [16384x4096]@[4096x1024] -> g_y (fp32)
    hgemm<false, false><<<dim3(D_DIM / 256, NK / 128), 256, SMEM_DYN>>>(
        hbuf, w2t, ybuf, FF_DIM, D_DIM);

    // 5) weighted combine into d_out
    combine_kernel<<<(N_TOK * (D_DIM / 4)) / 256, 256>>>(out);
}

// round 17
// speedup vs baseline: 1.0440x; 1.0440x over previous
#include <cuda_runtime.h>
#include <cuda_fp16.h>
#include <math.h>
#include <stdint.h>

// Static problem config
#define N_TOK 8192      // B*T = 4*2048
#define D_DIM 1024
#define FF_DIM 4096
#define N_EXP 8
#define NK 16384        // N_TOK * TOP_K
#define CHUNK 2048      // NK / N_EXP
#define STAGES 3

// ---------------- device scratch (no allocations allowed) ----------------
__device__ __align__(256) __half g_h[(size_t)NK * FF_DIM];      // fp16 gelu(perm @ w1)
__device__ __align__(256) __half g_y[(size_t)NK * D_DIM];       // fp16 h @ w2
__device__ __align__(256) __half g_xh[(size_t)N_TOK * D_DIM];   // fp16(x)
__device__ __align__(256) __half g_w1t[(size_t)N_EXP * (size_t)FF_DIM * D_DIM]; // w1^T fp16
__device__ __align__(256) __half g_w2t[(size_t)N_EXP * (size_t)D_DIM * FF_DIM]; // w2^T fp16
__device__ int   g_eflat[NK];
__device__ float g_wflat[NK];
__device__ int   g_dest[NK];
__device__ int   g_srcrow[NK];

// ---------------- helpers ----------------
__device__ __forceinline__ uint32_t smem_u32(const void* p) {
    return (uint32_t)__cvta_generic_to_shared(p);
}
__device__ __forceinline__ void cp16(uint32_t dst, const void* src) {
    asm volatile("cp.async.cg.shared.global [%0], [%1], 16;" :: "r"(dst), "l"(src));
}
#define LDSM_X4(r0, r1, r2, r3, a) \
    asm volatile("ldmatrix.sync.aligned.m8n8.x4.shared.b16 {%0,%1,%2,%3}, [%4];" \
                 : "=r"(r0), "=r"(r1), "=r"(r2), "=r"(r3) : "r"(a))

// ---------------- 0) weight transpose + fp16 convert: w[E][K][N] -> wt[E][N][K] ----------------
__global__ void transpose_h(const float* __restrict__ w, __half* __restrict__ wt,
                            int K, int N) {
    __shared__ float t[32][33];
    int e = blockIdx.z;
    const float* we = w + (size_t)e * K * N;
    __half* wte = wt + (size_t)e * (size_t)N * K;
    int n0 = blockIdx.x * 32, k0 = blockIdx.y * 32;
    int tx = threadIdx.x, ty = threadIdx.y;  // 32 x 8
#pragma unroll
    for (int i = 0; i < 4; i++)
        t[ty + 8 * i][tx] = we[(size_t)(k0 + ty + 8 * i) * N + n0 + tx];
    __syncthreads();
#pragma unroll
    for (int i = 0; i < 4; i++)
        wte[(size_t)(n0 + ty + 8 * i) * K + k0 + tx] = __float2half_rn(t[tx][ty + 8 * i]);
}

// ---------------- 1) router: logits, top-2, softmax; also emits fp16(x) ----------------
__global__ void router_kernel(const float* __restrict__ x,
                              const float* __restrict__ rw) {
    __shared__ float s_rw[N_EXP * D_DIM];
    int tid = threadIdx.x;
    for (int i = tid; i < N_EXP * D_DIM; i += blockDim.x) s_rw[i] = rw[i];
    __syncthreads();

    int warp = tid >> 5, lane = tid & 31;
    int token = blockIdx.x * (blockDim.x >> 5) + warp;

    const float4* x4 = reinterpret_cast<const float4*>(x + (size_t)token * D_DIM);
    __half2* xh2 = reinterpret_cast<__half2*>(g_xh + (size_t)token * D_DIM);
    float acc[N_EXP];
#pragma unroll
    for (int e = 0; e < N_EXP; e++) acc[e] = 0.f;

    for (int dq = lane; dq < D_DIM / 4; dq += 32) {
        float4 xv = x4[dq];
        xh2[2 * dq]     = __floats2half2_rn(xv.x, xv.y);
        xh2[2 * dq + 1] = __floats2half2_rn(xv.z, xv.w);
#pragma unroll
        for (int e = 0; e < N_EXP; e++) {
            float4 r = reinterpret_cast<const float4*>(s_rw + e * D_DIM)[dq];
            acc[e] += xv.x * r.x + xv.y * r.y + xv.z * r.z + xv.w * r.w;
        }
    }
#pragma unroll
    for (int e = 0; e < N_EXP; e++)
#pragma unroll
        for (int off = 16; off > 0; off >>= 1)
            acc[e] += __shfl_xor_sync(0xffffffffu, acc[e], off);

    if (lane == 0) {
        int i0 = 0; float v0 = acc[0];
#pragma unroll
        for (int e = 1; e < N_EXP; e++) if (acc[e] > v0) { v0 = acc[e]; i0 = e; }
        int i1 = -1; float v1 = -INFINITY;
#pragma unroll
        for (int e = 0; e < N_EXP; e++)
            if (e != i0 && acc[e] > v1) { v1 = acc[e]; i1 = e; }
        float e1 = expf(v1 - v0);
        float inv = 1.f / (1.f + e1);
        g_eflat[2 * token]     = i0;
        g_eflat[2 * token + 1] = i1;
        g_wflat[2 * token]     = inv;
        g_wflat[2 * token + 1] = e1 * inv;
    }
}

// ---------------- 2) stable sort-by-expert rank scan: 3-phase, 1 block x 1024 ----------------
// 512 chunks of 32 elements. Phase A: per-chunk expert histograms (parallel).
// Phase B: per-expert serial exclusive prefix over chunks + expert bases.
// Phase C: placement using chunk prefix + in-chunk stable rank.
__global__ void scan_kernel() {
    __shared__ int s_hist[512][N_EXP];   // 16 KB
    __shared__ int s_base[N_EXP];
    __shared__ int s_tot[N_EXP];
    int tid = threadIdx.x;               // 1024 threads
    int warp = tid >> 5, lane = tid & 31;

    // zero histograms
    for (int i = tid; i < 512 * N_EXP; i += 1024) ((int*)s_hist)[i] = 0;
    __syncthreads();

    // Phase A: per-chunk histograms (warp w owns chunks w*16..w*16+15)
#pragma unroll 1
    for (int q = 0; q < 16; q++) {
        int c = warp * 16 + q;
        int e = g_eflat[c * 32 + lane];
        unsigned mask = __match_any_sync(0xffffffffu, e);
        if (lane == __ffs(mask) - 1) s_hist[c][e] = __popc(mask);
    }
    __syncthreads();

    // Phase B: per-expert exclusive prefix over 512 chunks (8 threads, serial)
    if (tid < N_EXP) {
        int run = 0;
#pragma unroll 1
        for (int c = 0; c < 512; c++) {
            int t = s_hist[c][tid];
            s_hist[c][tid] = run;
            run += t;
        }
        s_tot[tid] = run;
    }
    __syncthreads();
    if (tid == 0) {
        int off = 0;
        for (int e = 0; e < N_EXP; e++) { s_base[e] = off; off += s_tot[e]; }
    }
    __syncthreads();

    // Phase C: placement
#pragma unroll 1
    for (int q = 0; q < 16; q++) {
        int c = warp * 16 + q;
        int i = c * 32 + lane;
        int e = g_eflat[i];
        unsigned mask = __match_any_sync(0xffffffffu, e);
        int rank = __popc(mask & ((1u << lane) - 1u));
        int p = s_base[e] + s_hist[c][e] + rank;
        g_dest[i] = p;
        g_srcrow[p] = i >> 1;
    }
}

// ---------------- 3) fp16 mma.sync GEMM (m16n8k16 HMMA) — R13-proven config ----------------
// C[M x N] = op(A-rows @ Bt[expert]^T), A/Bt fp16, Bt [E][N][K] K-major.
// BM=BN=128, BK=64 (128B rows), 3-stage cp.async, 8 warps x (64x32),
// fp32 accumulate. SW128 swizzle; ldmatrix.x4 b16 fragments.
template <bool GATHER, bool GELU_OUT>
__global__ void __launch_bounds__(256)
hgemm(const __half* __restrict__ A, const __half* __restrict__ Bt,
      __half* __restrict__ Cout, int K, int N) {
    extern __shared__ __align__(1024) char smem[];
    const uint32_t STAGE = 32768;        // 16KB A + 16KB B per stage

    int tid = threadIdx.x;
    int lane = tid & 31, wid = tid >> 5;
    int m0 = blockIdx.y * 128, n0 = blockIdx.x * 128;
    int expert = m0 / CHUNK;
    const __half* Be = Bt + (size_t)expert * (size_t)N * K;

    // ---- loader: 4 A rows + 4 B rows per thread, one 16B chunk each ----
    int lr = tid >> 3;          // row base 0..31 (rows lr + 32*i)
    int lc = tid & 7;           // 16B chunk (8 halves) within 128B row
    const __half* ap[4];
    const __half* bp[4];
#pragma unroll
    for (int i = 0; i < 4; i++) {
        int r = lr + 32 * i;
        long asrc = GATHER ? (long)g_srcrow[m0 + r] : (long)(m0 + r);
        ap[i] = A + asrc * (size_t)K + lc * 8;
        bp[i] = Be + (size_t)(n0 + r) * K + lc * 8;
    }
    uint32_t off0 = lr * 128 + lc * 16;
    uint32_t swz0 = off0 ^ ((off0 >> 3) & 0x70);   // SW128; +32 rows swizzle-invariant
    uint32_t sbase = smem_u32(smem);

    int nIter = K / 64;

    // ---- prologue ----
#pragma unroll
    for (int s = 0; s < STAGES - 1; ++s) {
        uint32_t ab = sbase + s * STAGE + swz0;
        int kk = s * 64;
#pragma unroll
        for (int i = 0; i < 4; i++) {
            cp16(ab + i * 4096, ap[i] + kk);
            cp16(ab + 16384 + i * 4096, bp[i] + kk);
        }
        asm volatile("cp.async.commit_group;");
    }

    // ---- compute-side lane addressing (b16 ldmatrix canonical) ----
    int wm = (wid & 1) * 64, wn = (wid >> 1) * 32;
    int  arow = wm + (lane & 7) + ((lane >> 3) & 1) * 8;   // + mt*16
    uint32_t acol = ((lane >> 4) & 1) * 16;                // byte: + ks*32
    uint32_t axor = (arow & 7) << 4;
    int  brow = wn + (lane & 7) + ((lane >> 3) & 1) * 8;   // + g*16
    uint32_t bcol = ((lane >> 4) & 1) * 16;                // byte: + ks*32
    uint32_t bxor = (brow & 7) << 4;

    float acc[4][4][4];
#pragma unroll
    for (int mt = 0; mt < 4; mt++)
#pragma unroll
        for (int nt = 0; nt < 4; nt++)
#pragma unroll
            for (int j = 0; j < 4; j++) acc[mt][nt][j] = 0.f;

#pragma unroll 1
    for (int it = 0; it < nIter; ++it) {
        asm volatile("cp.async.wait_group %0;" :: "n"(STAGES - 2));
        __syncthreads();

        int pre = it + STAGES - 1;
        if (pre < nIter) {
            uint32_t ab = sbase + (pre % STAGES) * STAGE + swz0;
            int kk = pre * 64;
#pragma unroll
            for (int i = 0; i < 4; i++) {
                cp16(ab + i * 4096, ap[i] + kk);
                cp16(ab + 16384 + i * 4096, bp[i] + kk);
            }
        }
        asm volatile("cp.async.commit_group;");

        uint32_t abase = sbase + (it % STAGES) * STAGE;
        uint32_t bbase = abase + 16384;
#pragma unroll
        for (int ks = 0; ks < 4; ++ks) {            // 4 x k16
            uint32_t af[4][4];
#pragma unroll
            for (int mt = 0; mt < 4; ++mt) {
                uint32_t addr = abase + (uint32_t)(arow + mt * 16) * 128
                              + (((uint32_t)ks * 32 + acol) ^ axor);
                LDSM_X4(af[mt][0], af[mt][1], af[mt][2], af[mt][3], addr);
            }
            uint32_t bf[8];
#pragma unroll
            for (int g = 0; g < 2; ++g) {           // two n8 tiles per x4
                uint32_t addr = bbase + (uint32_t)(brow + g * 16) * 128
                              + (((uint32_t)ks * 32 + bcol) ^ bxor);
                LDSM_X4(bf[g * 4 + 0], bf[g * 4 + 1], bf[g * 4 + 2], bf[g * 4 + 3], addr);
            }
#pragma unroll
            for (int mt = 0; mt < 4; ++mt)
#pragma unroll
                for (int nt = 0; nt < 4; ++nt) {
                    float* c = acc[mt][nt];
                    uint32_t b0 = bf[(nt >> 1) * 4 + (nt & 1)];
                    uint32_t b1 = bf[(nt >> 1) * 4 + (nt & 1) + 2];
                    asm volatile(
                        "mma.sync.aligned.m16n8k16.row.col.f32.f16.f16.f32 "
                        "{%0,%1,%2,%3}, {%4,%5,%6,%7}, {%8,%9}, {%0,%1,%2,%3};"
                        : "+f"(c[0]), "+f"(c[1]), "+f"(c[2]), "+f"(c[3])
                        : "r"(af[mt][0]), "r"(af[mt][1]), "r"(af[mt][2]), "r"(af[mt][3]),
                          "r"(b0), "r"(b1));
                }
        }
    }

    // ---- epilogue: fp16 stores (gelu fused for GEMM1) ----
#pragma unroll
    for (int mt = 0; mt < 4; ++mt) {
        int r0 = m0 + wm + mt * 16 + (lane >> 2);
#pragma unroll
        for (int nt = 0; nt < 4; ++nt) {
            int cc = n0 + wn + nt * 8 + (lane & 3) * 2;
            float v[4];
#pragma unroll
            for (int j = 0; j < 4; j++) {
                float t = acc[mt][nt][j];
                if (GELU_OUT) t = 0.5f * t * (1.f + erff(t * 0.70710678118654752f));
                v[j] = t;
            }
            *reinterpret_cast<__half2*>(Cout + (size_t)r0 * N + cc)
                = __floats2half2_rn(v[0], v[1]);
            *reinterpret_cast<__half2*>(Cout + (size_t)(r0 + 8) * N + cc)
                = __floats2half2_rn(v[2], v[3]);
        }
    }
}

// ---------------- 4) weighted unpermute via gather (deterministic) ----------------
// each thread: one token x 8 columns (uint4 = 8 halves)
__global__ void combine_kernel(float* __restrict__ out) {
    int idx = blockIdx.x * blockDim.x + threadIdx.x;   // over N_TOK * (D/8)
    int n  = idx >> 7;          // D/8 = 128
    int dq = idx & 127;
    int p0 = g_dest[2 * n], p1 = g_dest[2 * n + 1];
    float w0 = g_wflat[2 * n], w1 = g_wflat[2 * n + 1];
    uint4 u0 = reinterpret_cast<const uint4*>(g_y + (size_t)p0 * D_DIM)[dq];
    uint4 u1 = reinterpret_cast<const uint4*>(g_y + (size_t)p1 * D_DIM)[dq];
    const __half2* h0 = reinterpret_cast<const __half2*>(&u0);
    const __half2* h1 = reinterpret_cast<const __half2*>(&u1);
    float4 r[2];
#pragma unroll
    for (int q = 0; q < 4; q++) {
        float2 a = __half22float2(h0[q]);
        float2 b = __half22float2(h1[q]);
        ((float2*)r)[q] = make_float2(w0 * a.x + w1 * b.x, w0 * a.y + w1 * b.y);
    }
    float4* o = reinterpret_cast<float4*>(out + (size_t)n * D_DIM + dq * 8);
    o[0] = r[0];
    o[1] = r[1];
}

// ---------------- launch ----------------
extern "C" void kernel_launch(void* const* d_in, const int* in_sizes, int n_in,
                              void* d_out, int out_size) {
    const float* x  = (const float*)d_in[0];   // [8192, 1024]
    const float* rw = (const float*)d_in[1];   // [8, 1024]
    const float* w1 = (const float*)d_in[2];   // [8, 1024, 4096]
    const float* w2 = (const float*)d_in[3];   // [8, 4096, 1024]
    float* out = (float*)d_out;                // [8192, 1024]

    __half *w1t, *w2t, *hbuf, *ybuf, *xh;
    cudaGetSymbolAddress((void**)&w1t, g_w1t);
    cudaGetSymbolAddress((void**)&w2t, g_w2t);
    cudaGetSymbolAddress((void**)&hbuf, g_h);
    cudaGetSymbolAddress((void**)&ybuf, g_y);
    cudaGetSymbolAddress((void**)&xh, g_xh);

    const int SMEM_DYN = STAGES * 32768;   // 96 KB
    cudaFuncSetAttribute(hgemm<true, true>,
                         cudaFuncAttributeMaxDynamicSharedMemorySize, SMEM_DYN);
    cudaFuncSetAttribute(hgemm<false, false>,
                         cudaFuncAttributeMaxDynamicSharedMemorySize, SMEM_DYN);

    // 0) fp16 weights (+transpose)
    transpose_h<<<dim3(FF_DIM / 32, D_DIM / 32, N_EXP), dim3(32, 8)>>>(w1, w1t, D_DIM, FF_DIM);
    transpose_h<<<dim3(D_DIM / 32, FF_DIM / 32, N_EXP), dim3(32, 8)>>>(w2, w2t, FF_DIM, D_DIM);

    // 1) router (fp32 logits) + fp16(x) emission
    router_kernel<<<N_TOK / 32, 1024>>>(x, rw);

    // 2) stable expert-rank scan (3-phase)
    scan_kernel<<<1, 1024>>>();

    // 3) GEMM1: gather + [16384x1024]@[1024x4096] + gelu -> g_h (fp16)
    hgemm<true, true><<<dim3(FF_DIM / 128, NK / 128), 256, SMEM_DYN>>>(
        xh, w1t, hbuf, D_DIM, FF_DIM);

    // 4) GEMM2: [16384x4096]@[4096x1024] -> g_y (fp16)
    hgemm<false, false><<<dim3(D_DIM / 128, NK / 128), 256, SMEM_DYN>>>(
        hbuf, w2t, ybuf, FF_DIM, D_DIM);

    // 5) weighted combine into d_out
    combine_kernel<<<(N_TOK * (D_DIM / 8)) / 256, 256>>>(out);
}